// round 15
// baseline (speedup 1.0000x reference)
#include <cuda_runtime.h>
#include <cuda_fp16.h>
#include <cstdint>

// ---------------------------------------------------------------------------
// CompressiveMemory via HMMA (mma.sync f16, fp32 accum), single-fp16 operands.
// Round-12 bodies (proven 126.8us) run by 296 persistent blocks with dynamic
// work stealing (kills wave quantization + tail imbalance).
// ---------------------------------------------------------------------------

#define B_SZ 2
#define H_SZ 32
#define T_SZ 4096
#define D_SZ 128
#define NCHUNK 8
#define CHUNK_T (T_SZ / NCHUNK)

#define OUT_ELEMS ((size_t)B_SZ * H_SZ * T_SZ * D_SZ)
#define MNEW_ELEMS (H_SZ * D_SZ * D_SZ)
#define ZNEW_ELEMS (H_SZ * D_SZ)

#define B_IMG 34816
#define N_WORK 512
#define GRID_PERSIST 296

__device__ __align__(16) unsigned char g_Bimg[H_SZ * B_IMG];
__device__ __align__(16) float g_partM[H_SZ * NCHUNK * D_SZ * D_SZ];
__device__ __align__(16) float g_partZ[H_SZ * NCHUNK * D_SZ];
__device__ int g_work;

__device__ __forceinline__ uint32_t pkh2(float lo, float hi) {
    uint32_t d;
    asm("cvt.rn.f16x2.f32 %0, %2, %1;" : "=r"(d) : "f"(lo), "f"(hi));
    return d;
}
// phi on packed f16x2, branch-free: ex2(min(x,0)*log2e) + max(x,0)
__device__ __forceinline__ uint32_t phi2(uint32_t h) {
    uint32_t neg, pos, e, r;
    asm("min.f16x2 %0, %1, %2;" : "=r"(neg) : "r"(h), "r"(0u));
    asm("max.f16x2 %0, %1, %2;" : "=r"(pos) : "r"(h), "r"(0u));
    asm("mul.rn.f16x2 %0, %1, %2;" : "=r"(e) : "r"(neg), "r"(0x3DC53DC5u));
    asm("ex2.approx.f16x2 %0, %0;" : "+r"(e));
    asm("add.rn.f16x2 %0, %1, %2;" : "=r"(r) : "r"(e), "r"(pos));
    return r;
}
__device__ __forceinline__ uint32_t havg(uint32_t a, uint32_t b) {
    uint32_t s, r;
    asm("add.rn.f16x2 %0, %1, %2;" : "=r"(s) : "r"(a), "r"(b));
    asm("mul.rn.f16x2 %0, %1, %2;" : "=r"(r) : "r"(s), "r"(0x38003800u));
    return r;
}
__device__ __forceinline__ float hlo(uint32_t w) {
    float f;
    asm("{.reg .f16 l,h; mov.b32 {l,h}, %1; cvt.f32.f16 %0, l;}" : "=f"(f) : "r"(w));
    return f;
}
__device__ __forceinline__ float hhi(uint32_t w) {
    float f;
    asm("{.reg .f16 l,h; mov.b32 {l,h}, %1; cvt.f32.f16 %0, h;}" : "=f"(f) : "r"(w));
    return f;
}
__device__ __forceinline__ uint32_t smem_u32(const void* p) {
    uint32_t a;
    asm("{ .reg .u64 t; cvta.to.shared.u64 t, %1; cvt.u32.u64 %0, t; }"
        : "=r"(a) : "l"(p));
    return a;
}

__device__ __forceinline__ void ldm4(uint32_t* r, uint32_t a) {
    asm volatile("ldmatrix.sync.aligned.m8n8.x4.shared.b16 {%0,%1,%2,%3}, [%4];"
                 : "=r"(r[0]), "=r"(r[1]), "=r"(r[2]), "=r"(r[3]) : "r"(a));
}
__device__ __forceinline__ void ldm4t(uint32_t* r, uint32_t a) {
    asm volatile("ldmatrix.sync.aligned.m8n8.x4.trans.shared.b16 {%0,%1,%2,%3}, [%4];"
                 : "=r"(r[0]), "=r"(r[1]), "=r"(r[2]), "=r"(r[3]) : "r"(a));
}
__device__ __forceinline__ void ldm2(uint32_t* r, uint32_t a) {
    asm volatile("ldmatrix.sync.aligned.m8n8.x2.shared.b16 {%0,%1}, [%2];"
                 : "=r"(r[0]), "=r"(r[1]) : "r"(a));
}
__device__ __forceinline__ void mma16816(float* c, const uint32_t* a,
                                         const uint32_t* b) {
    asm volatile(
        "mma.sync.aligned.m16n8k16.row.col.f32.f16.f16.f32 "
        "{%0,%1,%2,%3}, {%4,%5,%6,%7}, {%8,%9}, {%0,%1,%2,%3};"
        : "+f"(c[0]), "+f"(c[1]), "+f"(c[2]), "+f"(c[3])
        : "r"(a[0]), "r"(a[1]), "r"(a[2]), "r"(a[3]), "r"(b[0]), "r"(b[1]));
}
__device__ __forceinline__ void cpa16(uint32_t s, const void* g) {
    asm volatile("cp.async.cg.shared.global [%0], [%1], 16;" :: "r"(s), "l"(g));
}
#define CP_COMMIT() asm volatile("cp.async.commit_group;" ::: "memory")
#define CP_WAIT0()  asm volatile("cp.async.wait_group 0;" ::: "memory")

// swizzled byte offset inside a [rows][128 f16] tile (256B rows)
__device__ __forceinline__ uint32_t sw_off(int row, int kc4) {
    return (uint32_t)(row * 256 + ((((kc4 >> 1) ^ (row & 7)) << 4) | ((kc4 & 1) << 3)));
}

// ---------------------------------------------------------------------------
// prep (proven) + work-counter reset for graph replay
// ---------------------------------------------------------------------------
__device__ __forceinline__ void h_store(unsigned char* img, uint32_t off,
                                        float v0, float v1, float v2, float v3) {
    *(uint2*)(img + off) = make_uint2(pkh2(v0, v1), pkh2(v2, v3));
}

__global__ void __launch_bounds__(256) prep_kernel(const float* __restrict__ M,
                                                   const float* __restrict__ z)
{
    __shared__ float ps[32 * 129];
    const int h = blockIdx.x >> 2;
    const int q = blockIdx.x & 3;
    const int tid = threadIdx.x;
    if (blockIdx.x == 0 && tid == 0) g_work = 0;   // reset for this launch
    const float* Mh = M + (size_t)h * 16384 + (size_t)q * 32 * 128;

    #pragma unroll
    for (int i = tid; i < 1024; i += 256) {
        int kl = i >> 5, c4 = i & 31;
        float4 m = ((const float4*)Mh)[i];
        float* p = ps + kl * 129 + c4 * 4;
        p[0] = m.x; p[1] = m.y; p[2] = m.z; p[3] = m.w;
    }
    __syncthreads();

    unsigned char* img = g_Bimg + (size_t)h * B_IMG;
    #pragma unroll
    for (int i = tid; i < 1024; i += 256) {
        int n = i >> 3, j = i & 7;
        h_store(img, sw_off(n, q * 8 + j),
                ps[(j * 4 + 0) * 129 + n], ps[(j * 4 + 1) * 129 + n],
                ps[(j * 4 + 2) * 129 + n], ps[(j * 4 + 3) * 129 + n]);
    }
    if (tid < 8) {
        int kc = q * 8 + tid;
        float4 zv = *(const float4*)(z + h * 128 + kc * 4);
        h_store(img, sw_off(128, kc), zv.x, zv.y, zv.z, zv.w);
    }
    if (q == 0 && tid < 224) {
        *(uint64_t*)(img + 129 * 256 + tid * 8) = 0ULL;
    }
}

// ---------------------------------------------------------------------------
// work bodies (round-12, proven). 256 thr.
// ---------------------------------------------------------------------------
// retrieve smem layout (100KB)
#define RT_SM_B 0
#define RT_SM_A 34816
#define RT_SM_STG 67584      // half-tile: 64 rows x 512B = 32768
#define RT_SM_NORM 100352
#define RT_TILES 8
// update smem layout (80KB)
#define UP_A 0               // 32 t-rows x 256B = 8192
#define UP_B 8192
#define UP_STG 16384         // 4 tensors x 16384 (32 rows x 512B)
#define FUSED_SMEM 102400

__device__ __forceinline__ void retrieve_part(unsigned char* sm, uint32_t sb,
                                              const float* __restrict__ Q,
                                              float* __restrict__ out,
                                              int bid)
{
    const int tid = threadIdx.x;
    const int l = tid & 31;
    const int wid = tid >> 5;
    const int wr = wid & 1;
    const int wc = wid >> 1;
    const int bh = bid >> 2;
    const int h = bh & 31;
    const int tbase = (bid & 3) * (RT_TILES * 128);

    const char* Qb = (const char*)(Q + ((size_t)bh * T_SZ + tbase) * D_SZ);
    float* ob = out + ((size_t)bh * T_SZ + tbase) * D_SZ;

    // prologue: B image + half 0 of tile 0
    {
        const unsigned char* bimg = g_Bimg + (size_t)h * B_IMG;
        for (int i = tid; i < B_IMG / 16; i += 256)
            cpa16(sb + RT_SM_B + i * 16, bimg + (size_t)i * 16);
        for (int i = tid; i < 2048; i += 256)
            cpa16(sb + RT_SM_STG + i * 16, Qb + (size_t)i * 16);
        CP_COMMIT();
    }

    const int arowl = l & 15;
    const int ag = (l >> 4) & 1;
    const int a7 = arowl & 7;
    const int browl = (l & 7) + ((l >> 4) << 3);
    const int bg = (l >> 3) & 1;
    const int b7 = browl & 7;
    const int le = l & 15;
    const int zrow = 128 + (le & 7);
    const int zg = (le >> 3) & 1;
    const int z7 = zrow & 7;

    uint32_t aoffm[4], boffp[2];
    #pragma unroll
    for (int mi = 0; mi < 4; ++mi)
        aoffm[mi] = (uint32_t)((wr * 64 + mi * 16 + arowl) * 256);
    #pragma unroll
    for (int p = 0; p < 2; ++p)
        boffp[p] = (uint32_t)((wc * 32 + p * 16 + browl) * 256);
    const uint32_t zoff = (uint32_t)(zrow * 256);

    for (int tile = 0; tile < RT_TILES; ++tile) {
        // two half-tile converts (STG = 64 rows at a time)
        #pragma unroll
        for (int hh = 0; hh < 2; ++hh) {
            CP_WAIT0();
            __syncthreads();
            #pragma unroll
            for (int i = 0; i < 8; ++i) {
                int idx = tid + i * 256;
                int row = (hh << 6) + (idx >> 5);
                int c4 = idx & 31;
                float4 q = *(const float4*)(sm + RT_SM_STG + (size_t)idx * 16);
                uint32_t h01 = phi2(pkh2(q.x, q.y));
                uint32_t h23 = phi2(pkh2(q.z, q.w));
                *(uint2*)(sm + RT_SM_A + sw_off(row, c4)) = make_uint2(h01, h23);
            }
            __syncthreads();
            int nh = tile * 2 + hh + 1;          // next global half index
            if (nh < RT_TILES * 2) {
                const char* src = Qb + (size_t)nh * 32768;
                for (int i = tid; i < 2048; i += 256)
                    cpa16(sb + RT_SM_STG + i * 16, src + (size_t)i * 16);
                CP_COMMIT();
            }
        }

        float acc[4][4][4];
        float zac[4][4];
        #pragma unroll
        for (int mi = 0; mi < 4; ++mi) {
            #pragma unroll
            for (int nj = 0; nj < 4; ++nj)
                #pragma unroll
                for (int qq = 0; qq < 4; ++qq) acc[mi][nj][qq] = 0.f;
            #pragma unroll
            for (int qq = 0; qq < 4; ++qq) zac[mi][qq] = 0.f;
        }

        #pragma unroll
        for (int ks = 0; ks < 8; ++ks) {
            const int cb = ks * 2;
            const uint32_t ach = (uint32_t)((cb + ag) ^ a7) << 4;
            const uint32_t bch = (uint32_t)((cb + bg) ^ b7) << 4;

            uint32_t AF[4][4];
            #pragma unroll
            for (int mi = 0; mi < 4; ++mi)
                ldm4(AF[mi], sb + RT_SM_A + aoffm[mi] + ach);

            uint32_t BhF[4][2];
            #pragma unroll
            for (int p = 0; p < 2; ++p) {
                uint32_t r[4];
                ldm4(r, sb + RT_SM_B + boffp[p] + bch);
                BhF[2 * p][0] = r[0]; BhF[2 * p][1] = r[1];
                BhF[2 * p + 1][0] = r[2]; BhF[2 * p + 1][1] = r[3];
            }

            #pragma unroll
            for (int mi = 0; mi < 4; ++mi)
                #pragma unroll
                for (int nj = 0; nj < 4; ++nj)
                    mma16816(acc[mi][nj], AF[mi], BhF[nj]);

            if ((ks & 3) == wc) {
                const uint32_t zch = (uint32_t)((cb + zg) ^ z7) << 4;
                uint32_t zh[2];
                ldm2(zh, sb + RT_SM_B + zoff + zch);
                #pragma unroll
                for (int mi = 0; mi < 4; ++mi)
                    mma16816(zac[mi], AF[mi], zh);
            }
        }

        float* norms = (float*)(sm + RT_SM_NORM);   // [4][128]
        if ((l & 3) == 0) {
            #pragma unroll
            for (int mi = 0; mi < 4; ++mi) {
                int r = wr * 64 + mi * 16 + (l >> 2);
                norms[wc * 128 + r] = zac[mi][0];
                norms[wc * 128 + r + 8] = zac[mi][2];
            }
        }
        __syncthreads();

        #pragma unroll
        for (int mi = 0; mi < 4; ++mi) {
            int r = wr * 64 + mi * 16 + (l >> 2);
            float n1 = norms[r] + norms[128 + r] + norms[256 + r] + norms[384 + r];
            float n2 = norms[r + 8] + norms[128 + r + 8] + norms[256 + r + 8] +
                       norms[384 + r + 8];
            float i1 = 1.0f / fmaxf(n1, 1e-6f);
            float i2 = 1.0f / fmaxf(n2, 1e-6f);
            float* o1 = ob + (size_t)(tile * 128 + r) * 128 + wc * 32 + (l & 3) * 2;
            float* o2 = o1 + (size_t)8 * 128;
            #pragma unroll
            for (int nj = 0; nj < 4; ++nj) {
                *(float2*)(o1 + nj * 8) =
                    make_float2(acc[mi][nj][0] * i1, acc[mi][nj][1] * i1);
                *(float2*)(o2 + nj * 8) =
                    make_float2(acc[mi][nj][2] * i2, acc[mi][nj][3] * i2);
            }
        }
        __syncthreads();
    }
}

__device__ __forceinline__ void update_part(unsigned char* sm, uint32_t sb,
                                            const float* __restrict__ K,
                                            const float* __restrict__ V,
                                            int ubid)
{
    const int tid = threadIdx.x;
    const int l = tid & 31;
    const int wid = tid >> 5;
    const int wr = wid & 1;
    const int wc = wid >> 1;
    const int c = ubid & 7;
    const int h = ubid >> 3;

    const char* K0 = (const char*)(K + ((size_t)h * T_SZ + c * CHUNK_T) * D_SZ);
    const char* K1 = (const char*)(K + ((size_t)(H_SZ + h) * T_SZ + c * CHUNK_T) * D_SZ);
    const char* V0 = (const char*)(V + ((size_t)h * T_SZ + c * CHUNK_T) * D_SZ);
    const char* V1 = (const char*)(V + ((size_t)(H_SZ + h) * T_SZ + c * CHUNK_T) * D_SZ);

    // stage 0: 32 t-rows of all four tensors (1024 float4 each)
    for (int i = tid; i < 1024; i += 256) {
        cpa16(sb + UP_STG + i * 16, K0 + (size_t)i * 16);
        cpa16(sb + UP_STG + 16384 + i * 16, K1 + (size_t)i * 16);
        cpa16(sb + UP_STG + 32768 + i * 16, V0 + (size_t)i * 16);
        cpa16(sb + UP_STG + 49152 + i * 16, V1 + (size_t)i * 16);
    }
    CP_COMMIT();

    const int atr = (l & 7) + ((l >> 4) << 3);
    const int aag = (l >> 3) & 1;
    const int at7 = atr & 7;
    const int btr = (l & 7) + (((l >> 3) & 1) << 3);
    const int bbg = (l >> 4) & 1;
    const int bt7 = btr & 7;

    float acc[4][4][4];
    #pragma unroll
    for (int mi = 0; mi < 4; ++mi)
        #pragma unroll
        for (int nj = 0; nj < 4; ++nj)
            #pragma unroll
            for (int qq = 0; qq < 4; ++qq) acc[mi][nj][qq] = 0.f;
    float za0 = 0.f, za1 = 0.f, za2 = 0.f, za3 = 0.f;
    const int myc4 = tid & 31;

    for (int si = 0; si < 16; ++si) {
        CP_WAIT0();
        __syncthreads();

        // convert 32 t-rows (4 float4 per thread)
        #pragma unroll
        for (int i = 0; i < 4; ++i) {
            int idx = tid + i * 256;
            int row = idx >> 5;
            float4 k0 = *(const float4*)(sm + UP_STG + (size_t)idx * 16);
            float4 k1 = *(const float4*)(sm + UP_STG + 16384 + (size_t)idx * 16);
            uint32_t p01 = havg(phi2(pkh2(k0.x, k0.y)), phi2(pkh2(k1.x, k1.y)));
            uint32_t p23 = havg(phi2(pkh2(k0.z, k0.w)), phi2(pkh2(k1.z, k1.w)));
            za0 += hlo(p01); za1 += hhi(p01);
            za2 += hlo(p23); za3 += hhi(p23);
            uint32_t off = sw_off(row, myc4);
            *(uint2*)(sm + UP_A + off) = make_uint2(p01, p23);

            float4 v0 = *(const float4*)(sm + UP_STG + 32768 + (size_t)idx * 16);
            float4 v1 = *(const float4*)(sm + UP_STG + 49152 + (size_t)idx * 16);
            uint32_t b01 = havg(pkh2(v0.x, v0.y), pkh2(v1.x, v1.y));
            uint32_t b23 = havg(pkh2(v0.z, v0.w), pkh2(v1.z, v1.w));
            *(uint2*)(sm + UP_B + off) = make_uint2(b01, b23);
        }
        __syncthreads();

        if (si + 1 < 16) {
            size_t go = (size_t)(si + 1) * 16384;
            for (int i = tid; i < 1024; i += 256) {
                cpa16(sb + UP_STG + i * 16, K0 + go + (size_t)i * 16);
                cpa16(sb + UP_STG + 16384 + i * 16, K1 + go + (size_t)i * 16);
                cpa16(sb + UP_STG + 32768 + i * 16, V0 + go + (size_t)i * 16);
                cpa16(sb + UP_STG + 49152 + i * 16, V1 + go + (size_t)i * 16);
            }
            CP_COMMIT();
        }

        #pragma unroll
        for (int ks = 0; ks < 2; ++ks) {
            const int k0t = ks * 16;
            uint32_t AF[4][4];
            #pragma unroll
            for (int mi = 0; mi < 4; ++mi) {
                uint32_t ch = (uint32_t)(((wr * 8 + mi * 2 + aag) ^ at7) << 4);
                ldm4t(AF[mi], sb + UP_A + (uint32_t)((k0t + atr) * 256) + ch);
            }
            uint32_t BhF[4][2];
            #pragma unroll
            for (int p = 0; p < 2; ++p) {
                uint32_t ch = (uint32_t)(((wc * 4 + p * 2 + bbg) ^ bt7) << 4);
                uint32_t addr = (uint32_t)((k0t + btr) * 256) + ch;
                uint32_t r[4];
                ldm4t(r, sb + UP_B + addr);
                BhF[2 * p][0] = r[0]; BhF[2 * p][1] = r[1];
                BhF[2 * p + 1][0] = r[2]; BhF[2 * p + 1][1] = r[3];
            }
            #pragma unroll
            for (int mi = 0; mi < 4; ++mi)
                #pragma unroll
                for (int nj = 0; nj < 4; ++nj)
                    mma16816(acc[mi][nj], AF[mi], BhF[nj]);
        }
    }
    __syncthreads();

    // deterministic z reduction via smem (reuse stage region)
    float* zr = (float*)(sm + UP_STG);              // [8][128]
    *(float4*)(zr + (tid >> 5) * 128 + myc4 * 4) = make_float4(za0, za1, za2, za3);
    __syncthreads();
    if (tid < 128) {
        float s = 0.f;
        #pragma unroll
        for (int j = 0; j < 8; ++j) s += zr[j * 128 + tid];
        g_partZ[(h * NCHUNK + c) * 128 + tid] = s;
    }

    float* pm = g_partM + ((size_t)(h * NCHUNK + c) << 14);
    #pragma unroll
    for (int mi = 0; mi < 4; ++mi) {
        int r = wr * 64 + mi * 16 + (l >> 2);
        #pragma unroll
        for (int nj = 0; nj < 4; ++nj) {
            int col = wc * 32 + nj * 8 + (l & 3) * 2;
            *(float2*)(pm + (size_t)r * 128 + col) =
                make_float2(acc[mi][nj][0], acc[mi][nj][1]);
            *(float2*)(pm + (size_t)(r + 8) * 128 + col) =
                make_float2(acc[mi][nj][2], acc[mi][nj][3]);
        }
    }
}

// ---------------------------------------------------------------------------
// persistent driver: 296 blocks steal 512 work units
// ---------------------------------------------------------------------------
__global__ void __launch_bounds__(256, 2)
fused_hmma(const float* __restrict__ Q, const float* __restrict__ K,
           const float* __restrict__ V, float* __restrict__ out)
{
    extern __shared__ unsigned char sm[];
    const uint32_t sb = smem_u32(sm);
    __shared__ int s_w;

    for (;;) {
        __syncthreads();                 // all threads done with smem
        if (threadIdx.x == 0) s_w = atomicAdd(&g_work, 1);
        __syncthreads();
        int w = s_w;
        if (w >= N_WORK) break;
        if (w < 256) {
            retrieve_part(sm, sb, Q, out, w);
        } else {
            update_part(sm, sb, K, V, w - 256);
        }
    }
}

// ---------------------------------------------------------------------------
// fixed-order reduction of partials + M/z add
// ---------------------------------------------------------------------------
__global__ void reduce_kernel(const float* __restrict__ M,
                              const float* __restrict__ z,
                              float* __restrict__ outM,
                              float* __restrict__ outZ)
{
    int idx = blockIdx.x * 256 + threadIdx.x;
    if (idx < MNEW_ELEMS) {
        int h = idx >> 14;
        int r = idx & 16383;
        float s = M[idx];
        #pragma unroll
        for (int cc = 0; cc < NCHUNK; ++cc)
            s += g_partM[((size_t)(h * NCHUNK + cc) << 14) + r];
        outM[idx] = s;
    } else {
        int j = idx - MNEW_ELEMS;
        if (j < ZNEW_ELEMS) {
            int h = j >> 7;
            int d = j & 127;
            float s = z[j];
            #pragma unroll
            for (int cc = 0; cc < NCHUNK; ++cc)
                s += g_partZ[(h * NCHUNK + cc) * 128 + d];
            outZ[j] = s;
        }
    }
}

// ---------------------------------------------------------------------------
extern "C" void kernel_launch(void* const* d_in, const int* in_sizes, int n_in,
                              void* d_out, int out_size)
{
    const float* Q = (const float*)d_in[0];
    const float* K = (const float*)d_in[1];
    const float* V = (const float*)d_in[2];
    const float* M = (const float*)d_in[3];
    const float* z = (const float*)d_in[4];

    float* out  = (float*)d_out;
    float* outM = out + OUT_ELEMS;
    float* outZ = outM + MNEW_ELEMS;

    cudaFuncSetAttribute(fused_hmma,
                         cudaFuncAttributeMaxDynamicSharedMemorySize, FUSED_SMEM);

    prep_kernel<<<H_SZ * 4, 256>>>(M, z);
    fused_hmma<<<GRID_PERSIST, 256, FUSED_SMEM>>>(Q, K, V, out);
    int red_threads = MNEW_ELEMS + ZNEW_ELEMS;
    reduce_kernel<<<(red_threads + 255) / 256, 256>>>(M, z, outM, outZ);
}

// round 16
// speedup vs baseline: 1.4662x; 1.4662x over previous
#include <cuda_runtime.h>
#include <cuda_fp16.h>
#include <cstdint>

// ---------------------------------------------------------------------------
// CompressiveMemory via HMMA (mma.sync f16, fp32 accum), single-fp16 operands.
// Round-12 structure (proven 126.8us) + streaming (.cs) stores for write-once
// outputs (out, partials) to keep L2 for the Q/K/V read streams.
// ---------------------------------------------------------------------------

#define B_SZ 2
#define H_SZ 32
#define T_SZ 4096
#define D_SZ 128
#define NCHUNK 8
#define CHUNK_T (T_SZ / NCHUNK)

#define OUT_ELEMS ((size_t)B_SZ * H_SZ * T_SZ * D_SZ)
#define MNEW_ELEMS (H_SZ * D_SZ * D_SZ)
#define ZNEW_ELEMS (H_SZ * D_SZ)

#define B_IMG 34816

__device__ __align__(16) unsigned char g_Bimg[H_SZ * B_IMG];
__device__ __align__(16) float g_partM[H_SZ * NCHUNK * D_SZ * D_SZ];
__device__ __align__(16) float g_partZ[H_SZ * NCHUNK * D_SZ];

__device__ __forceinline__ uint32_t pkh2(float lo, float hi) {
    uint32_t d;
    asm("cvt.rn.f16x2.f32 %0, %2, %1;" : "=r"(d) : "f"(lo), "f"(hi));
    return d;
}
// phi on packed f16x2, branch-free: ex2(min(x,0)*log2e) + max(x,0)
__device__ __forceinline__ uint32_t phi2(uint32_t h) {
    uint32_t neg, pos, e, r;
    asm("min.f16x2 %0, %1, %2;" : "=r"(neg) : "r"(h), "r"(0u));
    asm("max.f16x2 %0, %1, %2;" : "=r"(pos) : "r"(h), "r"(0u));
    asm("mul.rn.f16x2 %0, %1, %2;" : "=r"(e) : "r"(neg), "r"(0x3DC53DC5u));
    asm("ex2.approx.f16x2 %0, %0;" : "+r"(e));
    asm("add.rn.f16x2 %0, %1, %2;" : "=r"(r) : "r"(e), "r"(pos));
    return r;
}
__device__ __forceinline__ uint32_t havg(uint32_t a, uint32_t b) {
    uint32_t s, r;
    asm("add.rn.f16x2 %0, %1, %2;" : "=r"(s) : "r"(a), "r"(b));
    asm("mul.rn.f16x2 %0, %1, %2;" : "=r"(r) : "r"(s), "r"(0x38003800u));
    return r;
}
__device__ __forceinline__ float hlo(uint32_t w) {
    float f;
    asm("{.reg .f16 l,h; mov.b32 {l,h}, %1; cvt.f32.f16 %0, l;}" : "=f"(f) : "r"(w));
    return f;
}
__device__ __forceinline__ float hhi(uint32_t w) {
    float f;
    asm("{.reg .f16 l,h; mov.b32 {l,h}, %1; cvt.f32.f16 %0, h;}" : "=f"(f) : "r"(w));
    return f;
}
__device__ __forceinline__ uint32_t smem_u32(const void* p) {
    uint32_t a;
    asm("{ .reg .u64 t; cvta.to.shared.u64 t, %1; cvt.u32.u64 %0, t; }"
        : "=r"(a) : "l"(p));
    return a;
}
// streaming (evict-first) stores for write-once data
__device__ __forceinline__ void stcs2(float* p, float x, float y) {
    asm volatile("st.global.cs.v2.f32 [%0], {%1, %2};" :: "l"(p), "f"(x), "f"(y)
                 : "memory");
}
__device__ __forceinline__ void stcs1(float* p, float x) {
    asm volatile("st.global.cs.f32 [%0], %1;" :: "l"(p), "f"(x) : "memory");
}

__device__ __forceinline__ void ldm4(uint32_t* r, uint32_t a) {
    asm volatile("ldmatrix.sync.aligned.m8n8.x4.shared.b16 {%0,%1,%2,%3}, [%4];"
                 : "=r"(r[0]), "=r"(r[1]), "=r"(r[2]), "=r"(r[3]) : "r"(a));
}
__device__ __forceinline__ void ldm4t(uint32_t* r, uint32_t a) {
    asm volatile("ldmatrix.sync.aligned.m8n8.x4.trans.shared.b16 {%0,%1,%2,%3}, [%4];"
                 : "=r"(r[0]), "=r"(r[1]), "=r"(r[2]), "=r"(r[3]) : "r"(a));
}
__device__ __forceinline__ void ldm2(uint32_t* r, uint32_t a) {
    asm volatile("ldmatrix.sync.aligned.m8n8.x2.shared.b16 {%0,%1}, [%2];"
                 : "=r"(r[0]), "=r"(r[1]) : "r"(a));
}
__device__ __forceinline__ void mma16816(float* c, const uint32_t* a,
                                         const uint32_t* b) {
    asm volatile(
        "mma.sync.aligned.m16n8k16.row.col.f32.f16.f16.f32 "
        "{%0,%1,%2,%3}, {%4,%5,%6,%7}, {%8,%9}, {%0,%1,%2,%3};"
        : "+f"(c[0]), "+f"(c[1]), "+f"(c[2]), "+f"(c[3])
        : "r"(a[0]), "r"(a[1]), "r"(a[2]), "r"(a[3]), "r"(b[0]), "r"(b[1]));
}
__device__ __forceinline__ void cpa16(uint32_t s, const void* g) {
    asm volatile("cp.async.cg.shared.global [%0], [%1], 16;" :: "r"(s), "l"(g));
}
#define CP_COMMIT() asm volatile("cp.async.commit_group;" ::: "memory")
#define CP_WAIT0()  asm volatile("cp.async.wait_group 0;" ::: "memory")

// swizzled byte offset inside a [rows][128 f16] tile (256B rows)
__device__ __forceinline__ uint32_t sw_off(int row, int kc4) {
    return (uint32_t)(row * 256 + ((((kc4 >> 1) ^ (row & 7)) << 4) | ((kc4 & 1) << 3)));
}

// ---------------------------------------------------------------------------
// prep (unchanged, proven)
// ---------------------------------------------------------------------------
__device__ __forceinline__ void h_store(unsigned char* img, uint32_t off,
                                        float v0, float v1, float v2, float v3) {
    *(uint2*)(img + off) = make_uint2(pkh2(v0, v1), pkh2(v2, v3));
}

__global__ void __launch_bounds__(256) prep_kernel(const float* __restrict__ M,
                                                   const float* __restrict__ z)
{
    __shared__ float ps[32 * 129];
    const int h = blockIdx.x >> 2;
    const int q = blockIdx.x & 3;
    const int tid = threadIdx.x;
    const float* Mh = M + (size_t)h * 16384 + (size_t)q * 32 * 128;

    #pragma unroll
    for (int i = tid; i < 1024; i += 256) {
        int kl = i >> 5, c4 = i & 31;
        float4 m = ((const float4*)Mh)[i];
        float* p = ps + kl * 129 + c4 * 4;
        p[0] = m.x; p[1] = m.y; p[2] = m.z; p[3] = m.w;
    }
    __syncthreads();

    unsigned char* img = g_Bimg + (size_t)h * B_IMG;
    #pragma unroll
    for (int i = tid; i < 1024; i += 256) {
        int n = i >> 3, j = i & 7;
        h_store(img, sw_off(n, q * 8 + j),
                ps[(j * 4 + 0) * 129 + n], ps[(j * 4 + 1) * 129 + n],
                ps[(j * 4 + 2) * 129 + n], ps[(j * 4 + 3) * 129 + n]);
    }
    if (tid < 8) {
        int kc = q * 8 + tid;
        float4 zv = *(const float4*)(z + h * 128 + kc * 4);
        h_store(img, sw_off(128, kc), zv.x, zv.y, zv.z, zv.w);
    }
    if (q == 0 && tid < 224) {
        *(uint64_t*)(img + 129 * 256 + tid * 8) = 0ULL;
    }
}

// ---------------------------------------------------------------------------
// fused kernel: even blocks retrieve, odd blocks update. 256 thr, 2 CTA/SM.
// ---------------------------------------------------------------------------
// retrieve smem layout (100KB)
#define RT_SM_B 0
#define RT_SM_A 34816
#define RT_SM_STG 67584      // half-tile: 64 rows x 512B = 32768
#define RT_SM_NORM 100352
#define RT_TILES 8
// update smem layout (80KB)
#define UP_A 0               // 32 t-rows x 256B = 8192
#define UP_B 8192
#define UP_STG 16384         // 4 tensors x 16384 (32 rows x 512B)
#define FUSED_SMEM 102400

__device__ __forceinline__ void retrieve_part(unsigned char* sm, uint32_t sb,
                                              const float* __restrict__ Q,
                                              float* __restrict__ out,
                                              int bid)
{
    const int tid = threadIdx.x;
    const int l = tid & 31;
    const int wid = tid >> 5;
    const int wr = wid & 1;
    const int wc = wid >> 1;
    const int bh = bid >> 2;
    const int h = bh & 31;
    const int tbase = (bid & 3) * (RT_TILES * 128);

    const char* Qb = (const char*)(Q + ((size_t)bh * T_SZ + tbase) * D_SZ);
    float* ob = out + ((size_t)bh * T_SZ + tbase) * D_SZ;

    // prologue: B image + half 0 of tile 0
    {
        const unsigned char* bimg = g_Bimg + (size_t)h * B_IMG;
        for (int i = tid; i < B_IMG / 16; i += 256)
            cpa16(sb + RT_SM_B + i * 16, bimg + (size_t)i * 16);
        for (int i = tid; i < 2048; i += 256)
            cpa16(sb + RT_SM_STG + i * 16, Qb + (size_t)i * 16);
        CP_COMMIT();
    }

    const int arowl = l & 15;
    const int ag = (l >> 4) & 1;
    const int a7 = arowl & 7;
    const int browl = (l & 7) + ((l >> 4) << 3);
    const int bg = (l >> 3) & 1;
    const int b7 = browl & 7;
    const int le = l & 15;
    const int zrow = 128 + (le & 7);
    const int zg = (le >> 3) & 1;
    const int z7 = zrow & 7;

    uint32_t aoffm[4], boffp[2];
    #pragma unroll
    for (int mi = 0; mi < 4; ++mi)
        aoffm[mi] = (uint32_t)((wr * 64 + mi * 16 + arowl) * 256);
    #pragma unroll
    for (int p = 0; p < 2; ++p)
        boffp[p] = (uint32_t)((wc * 32 + p * 16 + browl) * 256);
    const uint32_t zoff = (uint32_t)(zrow * 256);

    for (int tile = 0; tile < RT_TILES; ++tile) {
        // two half-tile converts (STG = 64 rows at a time)
        #pragma unroll
        for (int hh = 0; hh < 2; ++hh) {
            CP_WAIT0();
            __syncthreads();
            #pragma unroll
            for (int i = 0; i < 8; ++i) {
                int idx = tid + i * 256;
                int row = (hh << 6) + (idx >> 5);
                int c4 = idx & 31;
                float4 q = *(const float4*)(sm + RT_SM_STG + (size_t)idx * 16);
                uint32_t h01 = phi2(pkh2(q.x, q.y));
                uint32_t h23 = phi2(pkh2(q.z, q.w));
                *(uint2*)(sm + RT_SM_A + sw_off(row, c4)) = make_uint2(h01, h23);
            }
            __syncthreads();
            int nh = tile * 2 + hh + 1;          // next global half index
            if (nh < RT_TILES * 2) {
                const char* src = Qb + (size_t)nh * 32768;
                for (int i = tid; i < 2048; i += 256)
                    cpa16(sb + RT_SM_STG + i * 16, src + (size_t)i * 16);
                CP_COMMIT();
            }
        }

        float acc[4][4][4];
        float zac[4][4];
        #pragma unroll
        for (int mi = 0; mi < 4; ++mi) {
            #pragma unroll
            for (int nj = 0; nj < 4; ++nj)
                #pragma unroll
                for (int qq = 0; qq < 4; ++qq) acc[mi][nj][qq] = 0.f;
            #pragma unroll
            for (int qq = 0; qq < 4; ++qq) zac[mi][qq] = 0.f;
        }

        #pragma unroll
        for (int ks = 0; ks < 8; ++ks) {
            const int cb = ks * 2;
            const uint32_t ach = (uint32_t)((cb + ag) ^ a7) << 4;
            const uint32_t bch = (uint32_t)((cb + bg) ^ b7) << 4;

            uint32_t AF[4][4];
            #pragma unroll
            for (int mi = 0; mi < 4; ++mi)
                ldm4(AF[mi], sb + RT_SM_A + aoffm[mi] + ach);

            uint32_t BhF[4][2];
            #pragma unroll
            for (int p = 0; p < 2; ++p) {
                uint32_t r[4];
                ldm4(r, sb + RT_SM_B + boffp[p] + bch);
                BhF[2 * p][0] = r[0]; BhF[2 * p][1] = r[1];
                BhF[2 * p + 1][0] = r[2]; BhF[2 * p + 1][1] = r[3];
            }

            #pragma unroll
            for (int mi = 0; mi < 4; ++mi)
                #pragma unroll
                for (int nj = 0; nj < 4; ++nj)
                    mma16816(acc[mi][nj], AF[mi], BhF[nj]);

            if ((ks & 3) == wc) {
                const uint32_t zch = (uint32_t)((cb + zg) ^ z7) << 4;
                uint32_t zh[2];
                ldm2(zh, sb + RT_SM_B + zoff + zch);
                #pragma unroll
                for (int mi = 0; mi < 4; ++mi)
                    mma16816(zac[mi], AF[mi], zh);
            }
        }

        float* norms = (float*)(sm + RT_SM_NORM);   // [4][128]
        if ((l & 3) == 0) {
            #pragma unroll
            for (int mi = 0; mi < 4; ++mi) {
                int r = wr * 64 + mi * 16 + (l >> 2);
                norms[wc * 128 + r] = zac[mi][0];
                norms[wc * 128 + r + 8] = zac[mi][2];
            }
        }
        __syncthreads();

        #pragma unroll
        for (int mi = 0; mi < 4; ++mi) {
            int r = wr * 64 + mi * 16 + (l >> 2);
            float n1 = norms[r] + norms[128 + r] + norms[256 + r] + norms[384 + r];
            float n2 = norms[r + 8] + norms[128 + r + 8] + norms[256 + r + 8] +
                       norms[384 + r + 8];
            float i1 = 1.0f / fmaxf(n1, 1e-6f);
            float i2 = 1.0f / fmaxf(n2, 1e-6f);
            float* o1 = ob + (size_t)(tile * 128 + r) * 128 + wc * 32 + (l & 3) * 2;
            float* o2 = o1 + (size_t)8 * 128;
            #pragma unroll
            for (int nj = 0; nj < 4; ++nj) {
                stcs2(o1 + nj * 8, acc[mi][nj][0] * i1, acc[mi][nj][1] * i1);
                stcs2(o2 + nj * 8, acc[mi][nj][2] * i2, acc[mi][nj][3] * i2);
            }
        }
        __syncthreads();
    }
}

__device__ __forceinline__ void update_part(unsigned char* sm, uint32_t sb,
                                            const float* __restrict__ K,
                                            const float* __restrict__ V,
                                            int ubid)
{
    const int tid = threadIdx.x;
    const int l = tid & 31;
    const int wid = tid >> 5;
    const int wr = wid & 1;
    const int wc = wid >> 1;
    const int c = ubid & 7;
    const int h = ubid >> 3;

    const char* K0 = (const char*)(K + ((size_t)h * T_SZ + c * CHUNK_T) * D_SZ);
    const char* K1 = (const char*)(K + ((size_t)(H_SZ + h) * T_SZ + c * CHUNK_T) * D_SZ);
    const char* V0 = (const char*)(V + ((size_t)h * T_SZ + c * CHUNK_T) * D_SZ);
    const char* V1 = (const char*)(V + ((size_t)(H_SZ + h) * T_SZ + c * CHUNK_T) * D_SZ);

    // stage 0: 32 t-rows of all four tensors (1024 float4 each)
    for (int i = tid; i < 1024; i += 256) {
        cpa16(sb + UP_STG + i * 16, K0 + (size_t)i * 16);
        cpa16(sb + UP_STG + 16384 + i * 16, K1 + (size_t)i * 16);
        cpa16(sb + UP_STG + 32768 + i * 16, V0 + (size_t)i * 16);
        cpa16(sb + UP_STG + 49152 + i * 16, V1 + (size_t)i * 16);
    }
    CP_COMMIT();

    const int atr = (l & 7) + ((l >> 4) << 3);
    const int aag = (l >> 3) & 1;
    const int at7 = atr & 7;
    const int btr = (l & 7) + (((l >> 3) & 1) << 3);
    const int bbg = (l >> 4) & 1;
    const int bt7 = btr & 7;

    float acc[4][4][4];
    #pragma unroll
    for (int mi = 0; mi < 4; ++mi)
        #pragma unroll
        for (int nj = 0; nj < 4; ++nj)
            #pragma unroll
            for (int qq = 0; qq < 4; ++qq) acc[mi][nj][qq] = 0.f;
    float za0 = 0.f, za1 = 0.f, za2 = 0.f, za3 = 0.f;
    const int myc4 = tid & 31;

    for (int si = 0; si < 16; ++si) {
        CP_WAIT0();
        __syncthreads();

        // convert 32 t-rows (4 float4 per thread)
        #pragma unroll
        for (int i = 0; i < 4; ++i) {
            int idx = tid + i * 256;
            int row = idx >> 5;
            float4 k0 = *(const float4*)(sm + UP_STG + (size_t)idx * 16);
            float4 k1 = *(const float4*)(sm + UP_STG + 16384 + (size_t)idx * 16);
            uint32_t p01 = havg(phi2(pkh2(k0.x, k0.y)), phi2(pkh2(k1.x, k1.y)));
            uint32_t p23 = havg(phi2(pkh2(k0.z, k0.w)), phi2(pkh2(k1.z, k1.w)));
            za0 += hlo(p01); za1 += hhi(p01);
            za2 += hlo(p23); za3 += hhi(p23);
            uint32_t off = sw_off(row, myc4);
            *(uint2*)(sm + UP_A + off) = make_uint2(p01, p23);

            float4 v0 = *(const float4*)(sm + UP_STG + 32768 + (size_t)idx * 16);
            float4 v1 = *(const float4*)(sm + UP_STG + 49152 + (size_t)idx * 16);
            uint32_t b01 = havg(pkh2(v0.x, v0.y), pkh2(v1.x, v1.y));
            uint32_t b23 = havg(pkh2(v0.z, v0.w), pkh2(v1.z, v1.w));
            *(uint2*)(sm + UP_B + off) = make_uint2(b01, b23);
        }
        __syncthreads();

        if (si + 1 < 16) {
            size_t go = (size_t)(si + 1) * 16384;
            for (int i = tid; i < 1024; i += 256) {
                cpa16(sb + UP_STG + i * 16, K0 + go + (size_t)i * 16);
                cpa16(sb + UP_STG + 16384 + i * 16, K1 + go + (size_t)i * 16);
                cpa16(sb + UP_STG + 32768 + i * 16, V0 + go + (size_t)i * 16);
                cpa16(sb + UP_STG + 49152 + i * 16, V1 + go + (size_t)i * 16);
            }
            CP_COMMIT();
        }

        #pragma unroll
        for (int ks = 0; ks < 2; ++ks) {
            const int k0t = ks * 16;
            uint32_t AF[4][4];
            #pragma unroll
            for (int mi = 0; mi < 4; ++mi) {
                uint32_t ch = (uint32_t)(((wr * 8 + mi * 2 + aag) ^ at7) << 4);
                ldm4t(AF[mi], sb + UP_A + (uint32_t)((k0t + atr) * 256) + ch);
            }
            uint32_t BhF[4][2];
            #pragma unroll
            for (int p = 0; p < 2; ++p) {
                uint32_t ch = (uint32_t)(((wc * 4 + p * 2 + bbg) ^ bt7) << 4);
                uint32_t addr = (uint32_t)((k0t + btr) * 256) + ch;
                uint32_t r[4];
                ldm4t(r, sb + UP_B + addr);
                BhF[2 * p][0] = r[0]; BhF[2 * p][1] = r[1];
                BhF[2 * p + 1][0] = r[2]; BhF[2 * p + 1][1] = r[3];
            }
            #pragma unroll
            for (int mi = 0; mi < 4; ++mi)
                #pragma unroll
                for (int nj = 0; nj < 4; ++nj)
                    mma16816(acc[mi][nj], AF[mi], BhF[nj]);
        }
    }
    __syncthreads();

    // deterministic z reduction via smem (reuse stage region)
    float* zr = (float*)(sm + UP_STG);              // [8][128]
    *(float4*)(zr + (tid >> 5) * 128 + myc4 * 4) = make_float4(za0, za1, za2, za3);
    __syncthreads();
    if (tid < 128) {
        float s = 0.f;
        #pragma unroll
        for (int j = 0; j < 8; ++j) s += zr[j * 128 + tid];
        stcs1(&g_partZ[(h * NCHUNK + c) * 128 + tid], s);
    }

    float* pm = g_partM + ((size_t)(h * NCHUNK + c) << 14);
    #pragma unroll
    for (int mi = 0; mi < 4; ++mi) {
        int r = wr * 64 + mi * 16 + (l >> 2);
        #pragma unroll
        for (int nj = 0; nj < 4; ++nj) {
            int col = wc * 32 + nj * 8 + (l & 3) * 2;
            stcs2(pm + (size_t)r * 128 + col, acc[mi][nj][0], acc[mi][nj][1]);
            stcs2(pm + (size_t)(r + 8) * 128 + col, acc[mi][nj][2], acc[mi][nj][3]);
        }
    }
}

__global__ void __launch_bounds__(256, 2)
fused_hmma(const float* __restrict__ Q, const float* __restrict__ K,
           const float* __restrict__ V, float* __restrict__ out)
{
    extern __shared__ unsigned char sm[];
    const uint32_t sb = smem_u32(sm);
    const int bid = blockIdx.x;
    if ((bid & 1) == 0) {
        retrieve_part(sm, sb, Q, out, bid >> 1);
    } else {
        update_part(sm, sb, K, V, bid >> 1);
    }
}

// ---------------------------------------------------------------------------
// fixed-order reduction of partials + M/z add
// ---------------------------------------------------------------------------
__global__ void reduce_kernel(const float* __restrict__ M,
                              const float* __restrict__ z,
                              float* __restrict__ outM,
                              float* __restrict__ outZ)
{
    int idx = blockIdx.x * 256 + threadIdx.x;
    if (idx < MNEW_ELEMS) {
        int h = idx >> 14;
        int r = idx & 16383;
        float s = M[idx];
        #pragma unroll
        for (int cc = 0; cc < NCHUNK; ++cc)
            s += g_partM[((size_t)(h * NCHUNK + cc) << 14) + r];
        outM[idx] = s;
    } else {
        int j = idx - MNEW_ELEMS;
        if (j < ZNEW_ELEMS) {
            int h = j >> 7;
            int d = j & 127;
            float s = z[j];
            #pragma unroll
            for (int cc = 0; cc < NCHUNK; ++cc)
                s += g_partZ[(h * NCHUNK + cc) * 128 + d];
            outZ[j] = s;
        }
    }
}

// ---------------------------------------------------------------------------
extern "C" void kernel_launch(void* const* d_in, const int* in_sizes, int n_in,
                              void* d_out, int out_size)
{
    const float* Q = (const float*)d_in[0];
    const float* K = (const float*)d_in[1];
    const float* V = (const float*)d_in[2];
    const float* M = (const float*)d_in[3];
    const float* z = (const float*)d_in[4];

    float* out  = (float*)d_out;
    float* outM = out + OUT_ELEMS;
    float* outZ = outM + MNEW_ELEMS;

    cudaFuncSetAttribute(fused_hmma,
                         cudaFuncAttributeMaxDynamicSharedMemorySize, FUSED_SMEM);

    prep_kernel<<<H_SZ * 4, 256>>>(M, z);
    fused_hmma<<<512, 256, FUSED_SMEM>>>(Q, K, V, out);
    int red_threads = MNEW_ELEMS + ZNEW_ELEMS;
    reduce_kernel<<<(red_threads + 255) / 256, 256>>>(M, z, outM, outZ);
}